// round 6
// baseline (speedup 1.0000x reference)
#include <cuda_runtime.h>
#include <cuda_bf16.h>
#include <math.h>

#define Bb 256
#define Tt 300
#define XD 513
#define ZD 16
#define Hh 128
#define G4 512          // 4*H
#define Mrows (Tt*Bb)   // 76800

// ---- output layout (flat concat, float32) ----
#define OFF_Y        0ull
#define OFF_ZMEAN    39398400ull
#define OFF_ZLOGVAR  40627200ull
#define OFF_ZMEANP   41856000ull
#define OFF_ZLOGVARP 43084800ull
#define OFF_ZOUT     44313600ull

// ---- scratch (device globals; no allocation allowed) ----
__device__ float d_xT  [(size_t)Tt*Bb*XD];   // (T,B,XD)
__device__ float d_Gin [(size_t)Tt*Bb*G4];   // (T,B,512) input gate pre-activations
__device__ float d_WhhT[(size_t)Hh*G4];      // (128,512) transposed W_hh
__device__ float d_hall[(size_t)Tt*Bb*Hh];   // (T,B,128) LSTM outputs g
__device__ float d_zbuf[(size_t)Tt*Bb*ZD];   // (T,B,16)
__device__ float d_h1  [(size_t)Mrows*Hh];
__device__ float d_h2  [(size_t)Mrows*Hh];
__device__ float d_ytmp[(size_t)Mrows*XD];   // (T,B,XD)

__device__ __forceinline__ float sigmf(float x) { return 1.0f/(1.0f + expf(-x)); }

// ============ transpose x: (B,XD,T) -> (T,B,XD) ============
__global__ void transpose_x(const float* __restrict__ x, float* __restrict__ xT) {
    __shared__ float tile[32][33];
    int b = blockIdx.z;
    int t0 = blockIdx.x*32, d0 = blockIdx.y*32;
    for (int i = threadIdx.y; i < 32; i += 8) {
        int d = d0 + i, t = t0 + threadIdx.x;
        if (d < XD && t < Tt) tile[i][threadIdx.x] = x[((size_t)b*XD + d)*Tt + t];
    }
    __syncthreads();
    for (int i = threadIdx.y; i < 32; i += 8) {
        int t = t0 + i, d = d0 + threadIdx.x;
        if (t < Tt && d < XD) xT[((size_t)t*Bb + b)*XD + d] = tile[threadIdx.x][i];
    }
}

// ============ transpose y: (T,B,XD) -> (B,XD,T) ============
__global__ void transpose_y(const float* __restrict__ yt, float* __restrict__ y) {
    __shared__ float tile[32][33];
    int b = blockIdx.z;
    int t0 = blockIdx.x*32, d0 = blockIdx.y*32;
    for (int i = threadIdx.y; i < 32; i += 8) {
        int t = t0 + i, d = d0 + threadIdx.x;
        if (t < Tt && d < XD) tile[i][threadIdx.x] = yt[((size_t)t*Bb + b)*XD + d];
    }
    __syncthreads();
    for (int i = threadIdx.y; i < 32; i += 8) {
        int d = d0 + i, t = t0 + threadIdx.x;
        if (d < XD && t < Tt) y[((size_t)b*XD + d)*Tt + t] = tile[threadIdx.x][i];
    }
}

// ============ transpose W_hh: (512,128) -> (128,512) ============
__global__ void transpose_whh(const float* __restrict__ W, float* __restrict__ WT) {
    int idx = blockIdx.x*256 + threadIdx.x;   // 65536 total
    int j = idx >> 7, k = idx & 127;
    WT[k*G4 + j] = W[idx];
}

// ============ generic NT GEMM: C[m][n] = act(sum_k A[m][k]*Bm[n][k] + bias) ============
// A: MxK row-major, Bm: NxK row-major. act: 0=none 1=tanh 2=exp
__global__ void gemm_nt(const float* __restrict__ A, const float* __restrict__ Bm,
                        float* __restrict__ C, int M, int N, int K,
                        const float* __restrict__ bias1, const float* __restrict__ bias2,
                        int act) {
    __shared__ float As[16][68];
    __shared__ float Bs[16][68];
    int tid = threadIdx.y*16 + threadIdx.x;
    int m0 = blockIdx.y*64, n0 = blockIdx.x*64;
    int lr = tid >> 2;         // 0..63
    int lc = (tid & 3) * 4;    // 0,4,8,12
    float acc[4][4] = {};
    for (int k0 = 0; k0 < K; k0 += 16) {
        #pragma unroll
        for (int q = 0; q < 4; q++) {
            int k = k0 + lc + q;
            int m = m0 + lr;
            As[lc+q][lr] = (m < M && k < K) ? A[(size_t)m*K + k] : 0.0f;
            int n = n0 + lr;
            Bs[lc+q][lr] = (n < N && k < K) ? Bm[(size_t)n*K + k] : 0.0f;
        }
        __syncthreads();
        #pragma unroll
        for (int k = 0; k < 16; k++) {
            float4 a = *(const float4*)&As[k][threadIdx.y*4];
            float4 b = *(const float4*)&Bs[k][threadIdx.x*4];
            acc[0][0] += a.x*b.x; acc[0][1] += a.x*b.y; acc[0][2] += a.x*b.z; acc[0][3] += a.x*b.w;
            acc[1][0] += a.y*b.x; acc[1][1] += a.y*b.y; acc[1][2] += a.y*b.z; acc[1][3] += a.y*b.w;
            acc[2][0] += a.z*b.x; acc[2][1] += a.z*b.y; acc[2][2] += a.z*b.z; acc[2][3] += a.z*b.w;
            acc[3][0] += a.w*b.x; acc[3][1] += a.w*b.y; acc[3][2] += a.w*b.z; acc[3][3] += a.w*b.w;
        }
        __syncthreads();
    }
    #pragma unroll
    for (int i = 0; i < 4; i++) {
        int m = m0 + threadIdx.y*4 + i;
        if (m >= M) continue;
        #pragma unroll
        for (int j = 0; j < 4; j++) {
            int n = n0 + threadIdx.x*4 + j;
            if (n >= N) continue;
            float v = acc[i][j];
            if (bias1) v += bias1[n];
            if (bias2) v += bias2[n];
            if (act == 1)      v = tanhf(v);
            else if (act == 2) v = expf(v);
            C[(size_t)m*N + n] = v;
        }
    }
}

// ============ LSTM over reversed time, 4 batch rows per CTA ============
__global__ void lstm_bwd(const float* __restrict__ Gin, const float* __restrict__ WhhT,
                         float* __restrict__ hall) {
    __shared__ float h_s[4][Hh];
    __shared__ float c_s[4][Hh];
    __shared__ float w_s[16*G4];     // 32KB: 16 k-rows of WhhT
    __shared__ float gate_s[4][G4];  // 8KB
    int tid = threadIdx.x;           // 256
    int b0 = blockIdx.x * 4;
    for (int i = tid; i < 4*Hh; i += 256) { (&h_s[0][0])[i] = 0.0f; (&c_s[0][0])[i] = 0.0f; }
    __syncthreads();
    int jg = tid & 127;   // j group: columns 4*jg..4*jg+3
    int bh = tid >> 7;    // batch half: {2bh, 2bh+1}
    for (int t = Tt-1; t >= 0; t--) {
        const float* gin = Gin + ((size_t)t*Bb + b0)*G4;
        float4 acc0 = *(const float4*)(gin + (2*bh  )*G4 + 4*jg);
        float4 acc1 = *(const float4*)(gin + (2*bh+1)*G4 + 4*jg);
        for (int kc = 0; kc < Hh; kc += 16) {
            #pragma unroll
            for (int q = 0; q < 8; q++) {
                int idx = tid*4 + q*1024;
                *(float4*)&w_s[idx] = *(const float4*)&WhhT[(size_t)kc*G4 + idx];
            }
            __syncthreads();
            #pragma unroll
            for (int kk = 0; kk < 16; kk++) {
                float4 w = *(const float4*)&w_s[kk*G4 + 4*jg];
                float ha = h_s[2*bh  ][kc+kk];
                float hb = h_s[2*bh+1][kc+kk];
                acc0.x += w.x*ha; acc0.y += w.y*ha; acc0.z += w.z*ha; acc0.w += w.w*ha;
                acc1.x += w.x*hb; acc1.y += w.y*hb; acc1.z += w.z*hb; acc1.w += w.w*hb;
            }
            __syncthreads();
        }
        *(float4*)&gate_s[2*bh  ][4*jg] = acc0;
        *(float4*)&gate_s[2*bh+1][4*jg] = acc1;
        __syncthreads();
        #pragma unroll
        for (int r = 0; r < 2; r++) {
            int task = tid + r*256;
            int bi = task >> 7, u = task & 127;
            float gi = gate_s[bi][u];
            float gf = gate_s[bi][u+128];
            float gg = gate_s[bi][u+256];
            float go = gate_s[bi][u+384];
            float c = sigmf(gf)*c_s[bi][u] + sigmf(gi)*tanhf(gg);
            float h = sigmf(go)*tanhf(c);
            c_s[bi][u] = c;
            h_s[bi][u] = h;
            hall[((size_t)t*Bb + (b0+bi))*Hh + u] = h;
        }
        __syncthreads();
    }
}

// ============ inference scan (forward over t), one CTA per batch row ============
__global__ void inf_scan(const float* __restrict__ hall, const float* __restrict__ eps,
                         const float* __restrict__ Wzz, const float* __restrict__ bzz,
                         const float* __restrict__ Wim, const float* __restrict__ bim,
                         const float* __restrict__ Wil, const float* __restrict__ bil,
                         float* __restrict__ zbuf, float* __restrict__ out) {
    __shared__ float wzz_s[Hh*ZD], wim_s[ZD*Hh], wil_s[ZD*Hh];
    __shared__ float bzz_s[Hh], bim_s[ZD], bil_s[ZD];
    __shared__ float z_s[ZD], gt_s[Hh], red_s[32];
    int tid = threadIdx.x;  // 128
    int b = blockIdx.x;
    for (int i = tid; i < Hh*ZD; i += 128) { wzz_s[i] = Wzz[i]; wim_s[i] = Wim[i]; wil_s[i] = Wil[i]; }
    bzz_s[tid] = bzz[tid];
    if (tid < ZD) { bim_s[tid] = bim[tid]; bil_s[tid] = bil[tid]; z_s[tid] = 0.0f; }
    __syncthreads();
    int o = tid >> 2, p = tid & 3;
    for (int t = 0; t < Tt; t++) {
        float a = bzz_s[tid];
        #pragma unroll
        for (int k = 0; k < ZD; k++) a += z_s[k]*wzz_s[tid*ZD + k];
        float gt = 0.5f*(tanhf(a) + hall[((size_t)t*Bb + b)*Hh + tid]);
        gt_s[tid] = gt;
        __syncthreads();
        const float* wrow = (o < 16) ? (wim_s + o*Hh) : (wil_s + (o-16)*Hh);
        float s = 0.0f;
        #pragma unroll
        for (int k = 0; k < 32; k++) s += gt_s[p*32 + k]*wrow[p*32 + k];
        s += __shfl_xor_sync(0xFFFFFFFFu, s, 1);
        s += __shfl_xor_sync(0xFFFFFFFFu, s, 2);
        if (p == 0) red_s[o] = s;
        __syncthreads();
        if (tid < ZD) {
            float mean   = red_s[tid]      + bim_s[tid];
            float logvar = red_s[16 + tid] + bil_s[tid];
            size_t base = ((size_t)t*Bb + b)*ZD + tid;
            float z = mean + eps[base]*expf(0.5f*logvar);
            z_s[tid] = z;
            out[OFF_ZMEAN   + base] = mean;
            out[OFF_ZLOGVAR + base] = logvar;
            zbuf[base] = z;
            out[OFF_ZOUT + ((size_t)b*ZD + tid)*Tt + t] = z;
        }
        __syncthreads();
    }
}

// ============ small generation chain (16-dim MLPs), one row per thread ============
__global__ void gen_small(const float* __restrict__ zbuf,
                          const float* __restrict__ Wg1, const float* __restrict__ bg1,
                          const float* __restrict__ Wg2, const float* __restrict__ bg2,
                          const float* __restrict__ Wp1, const float* __restrict__ bp1,
                          const float* __restrict__ Wp2, const float* __restrict__ bp2,
                          const float* __restrict__ Wpm, const float* __restrict__ bpm,
                          const float* __restrict__ Wpl, const float* __restrict__ bpl,
                          float* __restrict__ out) {
    __shared__ float wg1[256], wg2[256], wp1[256], wp2[256], wpm[256], wpl[256];
    __shared__ float sb[96];
    int tid = threadIdx.x;  // 256
    wg1[tid] = Wg1[tid]; wg2[tid] = Wg2[tid]; wp1[tid] = Wp1[tid];
    wp2[tid] = Wp2[tid]; wpm[tid] = Wpm[tid]; wpl[tid] = Wpl[tid];
    if (tid < 16) {
        sb[tid]    = bg1[tid]; sb[16+tid] = bg2[tid]; sb[32+tid] = bp1[tid];
        sb[48+tid] = bp2[tid]; sb[64+tid] = bpm[tid]; sb[80+tid] = bpl[tid];
    }
    __syncthreads();
    size_t m = (size_t)blockIdx.x*256 + tid;
    float z[16], t1[16], gate[16], zp[16], zmp[16], zlv[16];
    #pragma unroll
    for (int q = 0; q < 4; q++) *(float4*)&z[q*4] = *(const float4*)(zbuf + m*16 + q*4);
    #pragma unroll
    for (int j = 0; j < 16; j++) {
        float s = sb[j];
        #pragma unroll
        for (int k = 0; k < 16; k++) s += z[k]*wg1[j*16+k];
        t1[j] = fmaxf(s, 0.0f);
    }
    #pragma unroll
    for (int j = 0; j < 16; j++) {
        float s = sb[16+j];
        #pragma unroll
        for (int k = 0; k < 16; k++) s += t1[k]*wg2[j*16+k];
        gate[j] = sigmf(s);
    }
    #pragma unroll
    for (int j = 0; j < 16; j++) {
        float s = sb[32+j];
        #pragma unroll
        for (int k = 0; k < 16; k++) s += z[k]*wp1[j*16+k];
        t1[j] = fmaxf(s, 0.0f);   // reuse t1 as p1 activation
    }
    #pragma unroll
    for (int j = 0; j < 16; j++) {
        float s = sb[48+j];
        #pragma unroll
        for (int k = 0; k < 16; k++) s += t1[k]*wp2[j*16+k];
        zp[j] = s;
    }
    #pragma unroll
    for (int j = 0; j < 16; j++) {
        float s = sb[64+j];
        #pragma unroll
        for (int k = 0; k < 16; k++) s += z[k]*wpm[j*16+k];
        zmp[j] = (1.0f - gate[j])*s + gate[j]*zp[j];
    }
    #pragma unroll
    for (int j = 0; j < 16; j++) t1[j] = fmaxf(zp[j], 0.0f);  // relu(z_prop)
    #pragma unroll
    for (int j = 0; j < 16; j++) {
        float s = sb[80+j];
        #pragma unroll
        for (int k = 0; k < 16; k++) s += t1[k]*wpl[j*16+k];
        float sp = (s > 20.0f) ? s : log1pf(expf(s));
        zlv[j] = logf(sp);
    }
    #pragma unroll
    for (int q = 0; q < 4; q++) {
        *(float4*)(out + OFF_ZMEANP   + m*16 + q*4) = *(float4*)&zmp[q*4];
        *(float4*)(out + OFF_ZLOGVARP + m*16 + q*4) = *(float4*)&zlv[q*4];
    }
}

// ============ h1 = tanh(z @ W_zx1^T + b): K=16, N=128; 4 rows per CTA ============
__global__ void h1_kernel(const float* __restrict__ zbuf, const float* __restrict__ W,
                          const float* __restrict__ bias, float* __restrict__ h1) {
    __shared__ float w_s[Hh*ZD];
    __shared__ float b_s[Hh];
    __shared__ float z_s[4][ZD];
    int tid = threadIdx.x;  // 512
    for (int i = tid; i < Hh*ZD; i += 512) w_s[i] = W[i];
    if (tid < Hh) b_s[tid] = bias[tid];
    size_t m0 = (size_t)blockIdx.x*4;
    if (tid < 64) (&z_s[0][0])[tid] = zbuf[m0*ZD + tid];
    __syncthreads();
    int r = tid >> 7, n = tid & 127;
    float a = b_s[n];
    #pragma unroll
    for (int k = 0; k < ZD; k++) a += z_s[r][k]*w_s[n*ZD + k];
    h1[(m0 + r)*Hh + n] = tanhf(a);
}

// =====================================================================
extern "C" void kernel_launch(void* const* d_in, const int* in_sizes, int n_in,
                              void* d_out, int out_size) {
    const float* x    = (const float*)d_in[0];
    const float* eps  = (const float*)d_in[1];
    const float* W_ih = (const float*)d_in[2];
    const float* W_hh = (const float*)d_in[3];
    const float* b_ih = (const float*)d_in[4];
    const float* b_hh = (const float*)d_in[5];
    const float* W_zz = (const float*)d_in[6];
    const float* b_zz = (const float*)d_in[7];
    const float* W_im = (const float*)d_in[8];
    const float* b_im = (const float*)d_in[9];
    const float* W_il = (const float*)d_in[10];
    const float* b_il = (const float*)d_in[11];
    const float* W_g1 = (const float*)d_in[12];
    const float* b_g1 = (const float*)d_in[13];
    const float* W_g2 = (const float*)d_in[14];
    const float* b_g2 = (const float*)d_in[15];
    const float* W_p1 = (const float*)d_in[16];
    const float* b_p1 = (const float*)d_in[17];
    const float* W_p2 = (const float*)d_in[18];
    const float* b_p2 = (const float*)d_in[19];
    const float* W_pm = (const float*)d_in[20];
    const float* b_pm = (const float*)d_in[21];
    const float* W_pl = (const float*)d_in[22];
    const float* b_pl = (const float*)d_in[23];
    const float* W_zx1= (const float*)d_in[24];
    const float* b_zx1= (const float*)d_in[25];
    const float* W_zx2= (const float*)d_in[26];
    const float* b_zx2= (const float*)d_in[27];
    const float* W_gy = (const float*)d_in[28];
    const float* b_gy = (const float*)d_in[29];
    float* out = (float*)d_out;

    float *xT, *Gin, *WhhT, *hall, *zbuf, *h1, *h2, *ytmp;
    cudaGetSymbolAddress((void**)&xT,   d_xT);
    cudaGetSymbolAddress((void**)&Gin,  d_Gin);
    cudaGetSymbolAddress((void**)&WhhT, d_WhhT);
    cudaGetSymbolAddress((void**)&hall, d_hall);
    cudaGetSymbolAddress((void**)&zbuf, d_zbuf);
    cudaGetSymbolAddress((void**)&h1,   d_h1);
    cudaGetSymbolAddress((void**)&h2,   d_h2);
    cudaGetSymbolAddress((void**)&ytmp, d_ytmp);

    dim3 tp_grid(10, 17, Bb), tp_blk(32, 8);
    transpose_x<<<tp_grid, tp_blk>>>(x, xT);

    // Gin = xT @ W_ih^T + b_ih + b_hh   (M=76800, N=512, K=513)
    gemm_nt<<<dim3(8, 1200), dim3(16, 16)>>>(xT, W_ih, Gin, Mrows, G4, XD, b_ih, b_hh, 0);

    transpose_whh<<<256, 256>>>(W_hh, WhhT);

    lstm_bwd<<<64, 256>>>(Gin, WhhT, hall);

    inf_scan<<<Bb, 128>>>(hall, eps, W_zz, b_zz, W_im, b_im, W_il, b_il, zbuf, out);

    gen_small<<<300, 256>>>(zbuf, W_g1, b_g1, W_g2, b_g2, W_p1, b_p1, W_p2, b_p2,
                            W_pm, b_pm, W_pl, b_pl, out);

    h1_kernel<<<Mrows/4, 512>>>(zbuf, W_zx1, b_zx1, h1);

    // h2 = tanh(h1 @ W_zx2^T + b)  (M=76800, N=128, K=128)
    gemm_nt<<<dim3(2, 1200), dim3(16, 16)>>>(h1, W_zx2, h2, Mrows, Hh, Hh, b_zx2, nullptr, 1);

    // ytmp = exp(h2 @ W_gy^T + b)  (M=76800, N=513, K=128)
    gemm_nt<<<dim3(9, 1200), dim3(16, 16)>>>(h2, W_gy, ytmp, Mrows, XD, Hh, b_gy, nullptr, 2);

    transpose_y<<<tp_grid, tp_blk>>>(ytmp, out);
}

// round 8
// speedup vs baseline: 1.9071x; 1.9071x over previous
#include <cuda_runtime.h>
#include <cuda_bf16.h>
#include <math.h>

#define Bb 256
#define Tt 300
#define XD 513
#define ZD 16
#define Hh 128
#define G4 512          // 4*H
#define Mrows (Tt*Bb)   // 76800
#define KP 528          // padded K for the big GEMM (multiple of 16, float4-aligned)

// ---- output layout (flat concat, float32) ----
#define OFF_Y        0ull
#define OFF_ZMEAN    39398400ull
#define OFF_ZLOGVAR  40627200ull
#define OFF_ZMEANP   41856000ull
#define OFF_ZLOGVARP 43084800ull
#define OFF_ZOUT     44313600ull

// ---- scratch (device globals; zero-initialized at module load => pad cols stay 0) ----
__device__ float d_xT  [(size_t)Mrows*KP];   // (T*B, 528) padded
__device__ float d_Wp  [(size_t)G4*KP];      // (512, 528) padded W_ih
__device__ float d_bc  [G4];                 // b_ih + b_hh
__device__ float d_Gin [(size_t)Mrows*G4];   // (T,B,512)
__device__ float d_WhhT[(size_t)Hh*G4];      // (128,512) transposed W_hh
__device__ float d_hall[(size_t)Mrows*Hh];   // (T,B,128)
__device__ float d_zbuf[(size_t)Mrows*ZD];   // (T,B,16)
__device__ float d_h1  [(size_t)Mrows*Hh];
__device__ float d_h2  [(size_t)Mrows*Hh];
__device__ float d_ytmp[(size_t)Mrows*XD];   // (T,B,XD)

__device__ __forceinline__ float sigmf(float x) { return 1.0f/(1.0f + expf(-x)); }

// ============ transpose x: (B,XD,T) -> (T*B, KP) padded ============
__global__ void transpose_x(const float* __restrict__ x, float* __restrict__ xT) {
    __shared__ float tile[32][33];
    int b = blockIdx.z;
    int t0 = blockIdx.x*32, d0 = blockIdx.y*32;
    for (int i = threadIdx.y; i < 32; i += 8) {
        int d = d0 + i, t = t0 + threadIdx.x;
        if (d < XD && t < Tt) tile[i][threadIdx.x] = x[((size_t)b*XD + d)*Tt + t];
    }
    __syncthreads();
    for (int i = threadIdx.y; i < 32; i += 8) {
        int t = t0 + i, d = d0 + threadIdx.x;
        if (t < Tt && d < XD) xT[((size_t)t*Bb + b)*KP + d] = tile[threadIdx.x][i];
    }
}

// ============ prep: pad W_ih into (512,KP), combine biases ============
__global__ void prep_w(const float* __restrict__ W, const float* __restrict__ bi,
                       const float* __restrict__ bh, float* __restrict__ Wp,
                       float* __restrict__ bc) {
    int idx = blockIdx.x*256 + threadIdx.x;
    if (idx < G4*XD) {
        int n = idx / XD, k = idx % XD;
        Wp[(size_t)n*KP + k] = W[idx];
    }
    if (idx < G4) bc[idx] = bi[idx] + bh[idx];
}

// ============ transpose y: (T,B,XD) -> (B,XD,T) ============
__global__ void transpose_y(const float* __restrict__ yt, float* __restrict__ y) {
    __shared__ float tile[32][33];
    int b = blockIdx.z;
    int t0 = blockIdx.x*32, d0 = blockIdx.y*32;
    for (int i = threadIdx.y; i < 32; i += 8) {
        int t = t0 + i, d = d0 + threadIdx.x;
        if (t < Tt && d < XD) tile[i][threadIdx.x] = yt[((size_t)t*Bb + b)*XD + d];
    }
    __syncthreads();
    for (int i = threadIdx.y; i < 32; i += 8) {
        int d = d0 + i, t = t0 + threadIdx.x;
        if (d < XD && t < Tt) y[((size_t)b*XD + d)*Tt + t] = tile[threadIdx.x][i];
    }
}

// ============ transpose W_hh: (512,128) -> (128,512) ============
__global__ void transpose_whh(const float* __restrict__ W, float* __restrict__ WT) {
    int idx = blockIdx.x*256 + threadIdx.x;   // 65536 total
    int j = idx >> 7, k = idx & 127;
    WT[k*G4 + j] = W[idx];
}

// ============ 128x128-tile NT SGEMM ============
// C[m][n] = act(sum_k A[m][k]*Bm[n][k] + bias), A: M x lda, Bm: N x ldb (row-major).
// Requires: K % 16 == 0, lda/ldb % 4 == 0 (aligned float4 rows).
// act: 0=none 1=tanh 2=exp. 256 threads, 8x8 fragments (split 4+4 for coalesced stores).
__global__ void __launch_bounds__(256, 2)
gemm128(const float* __restrict__ A, const float* __restrict__ Bm,
        float* __restrict__ C, int M, int N, int K,
        int lda, int ldb, int ldc,
        const float* __restrict__ bias, int act) {
    __shared__ float As[16][128];
    __shared__ float Bs[16][128];
    int tid = threadIdx.x;
    int m0 = blockIdx.y*128, n0 = blockIdx.x*128;
    int tm4 = (tid >> 4) * 4;       // 0..60
    int tn4 = (tid & 15) * 4;       // 0..60
    float acc[8][8] = {};
    for (int k0 = 0; k0 < K; k0 += 16) {
        #pragma unroll
        for (int i = 0; i < 2; i++) {
            int idx = tid*2 + i;
            int r = idx >> 2, q = idx & 3;
            float4 av = make_float4(0.f,0.f,0.f,0.f);
            int m = m0 + r;
            if (m < M) av = *(const float4*)(A + (size_t)m*lda + k0 + q*4);
            As[q*4+0][r]=av.x; As[q*4+1][r]=av.y; As[q*4+2][r]=av.z; As[q*4+3][r]=av.w;
            float4 bv = make_float4(0.f,0.f,0.f,0.f);
            int n = n0 + r;
            if (n < N) bv = *(const float4*)(Bm + (size_t)n*ldb + k0 + q*4);
            Bs[q*4+0][r]=bv.x; Bs[q*4+1][r]=bv.y; Bs[q*4+2][r]=bv.z; Bs[q*4+3][r]=bv.w;
        }
        __syncthreads();
        #pragma unroll
        for (int k = 0; k < 16; k++) {
            float a[8], b[8];
            *(float4*)&a[0] = *(const float4*)&As[k][tm4];
            *(float4*)&a[4] = *(const float4*)&As[k][tm4 + 64];
            *(float4*)&b[0] = *(const float4*)&Bs[k][tn4];
            *(float4*)&b[4] = *(const float4*)&Bs[k][tn4 + 64];
            #pragma unroll
            for (int i = 0; i < 8; i++)
                #pragma unroll
                for (int j = 0; j < 8; j++)
                    acc[i][j] += a[i]*b[j];
        }
        __syncthreads();
    }
    // epilogue: scalar stores, coalesced across the warp (tn4 spans contiguous 64 floats)
    #pragma unroll
    for (int i = 0; i < 8; i++) {
        int m = m0 + ((i < 4) ? (tm4 + i) : (64 + tm4 + i - 4));
        if (m >= M) continue;
        float* crow = C + (size_t)m*ldc;
        #pragma unroll
        for (int j = 0; j < 8; j++) {
            int n = n0 + ((j < 4) ? (tn4 + j) : (64 + tn4 + j - 4));
            if (n >= N) continue;
            float v = acc[i][j];
            if (bias) v += bias[n];
            if (act == 1)      v = tanhf(v);
            else if (act == 2) v = expf(v);
            crow[n] = v;
        }
    }
}

// ============ LSTM over reversed time, 4 batch rows per CTA, reg-prefetched weights ============
__global__ void lstm_bwd(const float* __restrict__ Gin, const float* __restrict__ WhhT,
                         float* __restrict__ hall) {
    __shared__ float h_s[4][Hh];
    __shared__ float c_s[4][Hh];
    __shared__ float w_s[16*G4];     // 32KB: 16 k-rows of WhhT
    __shared__ float gate_s[4][G4];  // 8KB
    int tid = threadIdx.x;           // 256
    int b0 = blockIdx.x * 4;
    for (int i = tid; i < 4*Hh; i += 256) { (&h_s[0][0])[i] = 0.0f; (&c_s[0][0])[i] = 0.0f; }
    __syncthreads();
    int jg = tid & 127;   // j group: columns 4*jg..4*jg+3
    int bh = tid >> 7;    // batch half: {2bh, 2bh+1}
    // prefetch chunk kc=0 into registers
    float4 r[8];
    #pragma unroll
    for (int q = 0; q < 8; q++)
        r[q] = *(const float4*)&WhhT[(size_t)tid*4 + q*1024];
    for (int t = Tt-1; t >= 0; t--) {
        const float* gin = Gin + ((size_t)t*Bb + b0)*G4;
        float4 acc0 = *(const float4*)(gin + (2*bh  )*G4 + 4*jg);
        float4 acc1 = *(const float4*)(gin + (2*bh+1)*G4 + 4*jg);
        for (int kc = 0; kc < Hh; kc += 16) {
            // commit prefetched chunk to smem
            #pragma unroll
            for (int q = 0; q < 8; q++)
                *(float4*)&w_s[tid*4 + q*1024] = r[q];
            __syncthreads();
            // prefetch next chunk (wraps to chunk 0 for next t) — overlaps compute
            int kn = (kc + 16 < Hh) ? kc + 16 : 0;
            #pragma unroll
            for (int q = 0; q < 8; q++)
                r[q] = *(const float4*)&WhhT[(size_t)kn*G4 + tid*4 + q*1024];
            #pragma unroll
            for (int kk = 0; kk < 16; kk++) {
                float4 w = *(const float4*)&w_s[kk*G4 + 4*jg];
                float ha = h_s[2*bh  ][kc+kk];
                float hb = h_s[2*bh+1][kc+kk];
                acc0.x += w.x*ha; acc0.y += w.y*ha; acc0.z += w.z*ha; acc0.w += w.w*ha;
                acc1.x += w.x*hb; acc1.y += w.y*hb; acc1.z += w.z*hb; acc1.w += w.w*hb;
            }
            __syncthreads();
        }
        *(float4*)&gate_s[2*bh  ][4*jg] = acc0;
        *(float4*)&gate_s[2*bh+1][4*jg] = acc1;
        __syncthreads();
        #pragma unroll
        for (int rr = 0; rr < 2; rr++) {
            int task = tid + rr*256;
            int bi = task >> 7, u = task & 127;
            float gi = gate_s[bi][u];
            float gf = gate_s[bi][u+128];
            float gg = gate_s[bi][u+256];
            float go = gate_s[bi][u+384];
            float c = sigmf(gf)*c_s[bi][u] + sigmf(gi)*tanhf(gg);
            float h = sigmf(go)*tanhf(c);
            c_s[bi][u] = c;
            h_s[bi][u] = h;
            hall[((size_t)t*Bb + (b0+bi))*Hh + u] = h;
        }
        __syncthreads();
    }
}

// ============ inference scan (forward over t), one CTA per batch row ============
__global__ void inf_scan(const float* __restrict__ hall, const float* __restrict__ eps,
                         const float* __restrict__ Wzz, const float* __restrict__ bzz,
                         const float* __restrict__ Wim, const float* __restrict__ bim,
                         const float* __restrict__ Wil, const float* __restrict__ bil,
                         float* __restrict__ zbuf, float* __restrict__ out) {
    __shared__ float wzz_s[Hh*ZD], wim_s[ZD*Hh], wil_s[ZD*Hh];
    __shared__ float bzz_s[Hh], bim_s[ZD], bil_s[ZD];
    __shared__ float z_s[ZD], gt_s[Hh], red_s[32];
    int tid = threadIdx.x;  // 128
    int b = blockIdx.x;
    for (int i = tid; i < Hh*ZD; i += 128) { wzz_s[i] = Wzz[i]; wim_s[i] = Wim[i]; wil_s[i] = Wil[i]; }
    bzz_s[tid] = bzz[tid];
    if (tid < ZD) { bim_s[tid] = bim[tid]; bil_s[tid] = bil[tid]; z_s[tid] = 0.0f; }
    __syncthreads();
    int o = tid >> 2, p = tid & 3;
    for (int t = 0; t < Tt; t++) {
        float a = bzz_s[tid];
        #pragma unroll
        for (int k = 0; k < ZD; k++) a += z_s[k]*wzz_s[tid*ZD + k];
        float gt = 0.5f*(tanhf(a) + hall[((size_t)t*Bb + b)*Hh + tid]);
        gt_s[tid] = gt;
        __syncthreads();
        const float* wrow = (o < 16) ? (wim_s + o*Hh) : (wil_s + (o-16)*Hh);
        float s = 0.0f;
        #pragma unroll
        for (int k = 0; k < 32; k++) s += gt_s[p*32 + k]*wrow[p*32 + k];
        s += __shfl_xor_sync(0xFFFFFFFFu, s, 1);
        s += __shfl_xor_sync(0xFFFFFFFFu, s, 2);
        if (p == 0) red_s[o] = s;
        __syncthreads();
        if (tid < ZD) {
            float mean   = red_s[tid]      + bim_s[tid];
            float logvar = red_s[16 + tid] + bil_s[tid];
            size_t base = ((size_t)t*Bb + b)*ZD + tid;
            float z = mean + eps[base]*expf(0.5f*logvar);
            z_s[tid] = z;
            out[OFF_ZMEAN   + base] = mean;
            out[OFF_ZLOGVAR + base] = logvar;
            zbuf[base] = z;
            out[OFF_ZOUT + ((size_t)b*ZD + tid)*Tt + t] = z;
        }
        __syncthreads();
    }
}

// ============ small generation chain (16-dim MLPs), one row per thread ============
__global__ void gen_small(const float* __restrict__ zbuf,
                          const float* __restrict__ Wg1, const float* __restrict__ bg1,
                          const float* __restrict__ Wg2, const float* __restrict__ bg2,
                          const float* __restrict__ Wp1, const float* __restrict__ bp1,
                          const float* __restrict__ Wp2, const float* __restrict__ bp2,
                          const float* __restrict__ Wpm, const float* __restrict__ bpm,
                          const float* __restrict__ Wpl, const float* __restrict__ bpl,
                          float* __restrict__ out) {
    __shared__ float wg1[256], wg2[256], wp1[256], wp2[256], wpm[256], wpl[256];
    __shared__ float sb[96];
    int tid = threadIdx.x;  // 256
    wg1[tid] = Wg1[tid]; wg2[tid] = Wg2[tid]; wp1[tid] = Wp1[tid];
    wp2[tid] = Wp2[tid]; wpm[tid] = Wpm[tid]; wpl[tid] = Wpl[tid];
    if (tid < 16) {
        sb[tid]    = bg1[tid]; sb[16+tid] = bg2[tid]; sb[32+tid] = bp1[tid];
        sb[48+tid] = bp2[tid]; sb[64+tid] = bpm[tid]; sb[80+tid] = bpl[tid];
    }
    __syncthreads();
    size_t m = (size_t)blockIdx.x*256 + tid;
    float z[16], t1[16], gate[16], zp[16], zmp[16], zlv[16];
    #pragma unroll
    for (int q = 0; q < 4; q++) *(float4*)&z[q*4] = *(const float4*)(zbuf + m*16 + q*4);
    #pragma unroll
    for (int j = 0; j < 16; j++) {
        float s = sb[j];
        #pragma unroll
        for (int k = 0; k < 16; k++) s += z[k]*wg1[j*16+k];
        t1[j] = fmaxf(s, 0.0f);
    }
    #pragma unroll
    for (int j = 0; j < 16; j++) {
        float s = sb[16+j];
        #pragma unroll
        for (int k = 0; k < 16; k++) s += t1[k]*wg2[j*16+k];
        gate[j] = sigmf(s);
    }
    #pragma unroll
    for (int j = 0; j < 16; j++) {
        float s = sb[32+j];
        #pragma unroll
        for (int k = 0; k < 16; k++) s += z[k]*wp1[j*16+k];
        t1[j] = fmaxf(s, 0.0f);
    }
    #pragma unroll
    for (int j = 0; j < 16; j++) {
        float s = sb[48+j];
        #pragma unroll
        for (int k = 0; k < 16; k++) s += t1[k]*wp2[j*16+k];
        zp[j] = s;
    }
    #pragma unroll
    for (int j = 0; j < 16; j++) {
        float s = sb[64+j];
        #pragma unroll
        for (int k = 0; k < 16; k++) s += z[k]*wpm[j*16+k];
        zmp[j] = (1.0f - gate[j])*s + gate[j]*zp[j];
    }
    #pragma unroll
    for (int j = 0; j < 16; j++) t1[j] = fmaxf(zp[j], 0.0f);
    #pragma unroll
    for (int j = 0; j < 16; j++) {
        float s = sb[80+j];
        #pragma unroll
        for (int k = 0; k < 16; k++) s += t1[k]*wpl[j*16+k];
        float sp = (s > 20.0f) ? s : log1pf(expf(s));
        zlv[j] = logf(sp);
    }
    #pragma unroll
    for (int q = 0; q < 4; q++) {
        *(float4*)(out + OFF_ZMEANP   + m*16 + q*4) = *(float4*)&zmp[q*4];
        *(float4*)(out + OFF_ZLOGVARP + m*16 + q*4) = *(float4*)&zlv[q*4];
    }
}

// ============ h1 = tanh(z @ W_zx1^T + b): K=16, N=128; 4 rows per CTA ============
__global__ void h1_kernel(const float* __restrict__ zbuf, const float* __restrict__ W,
                          const float* __restrict__ bias, float* __restrict__ h1) {
    __shared__ float w_s[Hh*ZD];
    __shared__ float b_s[Hh];
    __shared__ float z_s[4][ZD];
    int tid = threadIdx.x;  // 512
    for (int i = tid; i < Hh*ZD; i += 512) w_s[i] = W[i];
    if (tid < Hh) b_s[tid] = bias[tid];
    size_t m0 = (size_t)blockIdx.x*4;
    if (tid < 64) (&z_s[0][0])[tid] = zbuf[m0*ZD + tid];
    __syncthreads();
    int r = tid >> 7, n = tid & 127;
    float a = b_s[n];
    #pragma unroll
    for (int k = 0; k < ZD; k++) a += z_s[r][k]*w_s[n*ZD + k];
    h1[(m0 + r)*Hh + n] = tanhf(a);
}

// =====================================================================
extern "C" void kernel_launch(void* const* d_in, const int* in_sizes, int n_in,
                              void* d_out, int out_size) {
    const float* x    = (const float*)d_in[0];
    const float* eps  = (const float*)d_in[1];
    const float* W_ih = (const float*)d_in[2];
    const float* W_hh = (const float*)d_in[3];
    const float* b_ih = (const float*)d_in[4];
    const float* b_hh = (const float*)d_in[5];
    const float* W_zz = (const float*)d_in[6];
    const float* b_zz = (const float*)d_in[7];
    const float* W_im = (const float*)d_in[8];
    const float* b_im = (const float*)d_in[9];
    const float* W_il = (const float*)d_in[10];
    const float* b_il = (const float*)d_in[11];
    const float* W_g1 = (const float*)d_in[12];
    const float* b_g1 = (const float*)d_in[13];
    const float* W_g2 = (const float*)d_in[14];
    const float* b_g2 = (const float*)d_in[15];
    const float* W_p1 = (const float*)d_in[16];
    const float* b_p1 = (const float*)d_in[17];
    const float* W_p2 = (const float*)d_in[18];
    const float* b_p2 = (const float*)d_in[19];
    const float* W_pm = (const float*)d_in[20];
    const float* b_pm = (const float*)d_in[21];
    const float* W_pl = (const float*)d_in[22];
    const float* b_pl = (const float*)d_in[23];
    const float* W_zx1= (const float*)d_in[24];
    const float* b_zx1= (const float*)d_in[25];
    const float* W_zx2= (const float*)d_in[26];
    const float* b_zx2= (const float*)d_in[27];
    const float* W_gy = (const float*)d_in[28];
    const float* b_gy = (const float*)d_in[29];
    float* out = (float*)d_out;

    float *xT, *Wp, *bc, *Gin, *WhhT, *hall, *zbuf, *h1, *h2, *ytmp;
    cudaGetSymbolAddress((void**)&xT,   d_xT);
    cudaGetSymbolAddress((void**)&Wp,   d_Wp);
    cudaGetSymbolAddress((void**)&bc,   d_bc);
    cudaGetSymbolAddress((void**)&Gin,  d_Gin);
    cudaGetSymbolAddress((void**)&WhhT, d_WhhT);
    cudaGetSymbolAddress((void**)&hall, d_hall);
    cudaGetSymbolAddress((void**)&zbuf, d_zbuf);
    cudaGetSymbolAddress((void**)&h1,   d_h1);
    cudaGetSymbolAddress((void**)&h2,   d_h2);
    cudaGetSymbolAddress((void**)&ytmp, d_ytmp);

    dim3 tp_grid(10, 17, Bb), tp_blk(32, 8);
    transpose_x<<<tp_grid, tp_blk>>>(x, xT);
    prep_w<<<(G4*XD + 255)/256, 256>>>(W_ih, b_ih, b_hh, Wp, bc);
    transpose_whh<<<256, 256>>>(W_hh, WhhT);

    // Gin = xT @ Wp^T + (b_ih + b_hh)   (M=76800, N=512, K=528 padded)
    gemm128<<<dim3(4, 600), 256>>>(xT, Wp, Gin, Mrows, G4, KP, KP, KP, G4, bc, 0);

    lstm_bwd<<<64, 256>>>(Gin, WhhT, hall);

    inf_scan<<<Bb, 128>>>(hall, eps, W_zz, b_zz, W_im, b_im, W_il, b_il, zbuf, out);

    gen_small<<<300, 256>>>(zbuf, W_g1, b_g1, W_g2, b_g2, W_p1, b_p1, W_p2, b_p2,
                            W_pm, b_pm, W_pl, b_pl, out);

    h1_kernel<<<Mrows/4, 512>>>(zbuf, W_zx1, b_zx1, h1);

    // h2 = tanh(h1 @ W_zx2^T + b)  (M=76800, N=128, K=128)
    gemm128<<<dim3(1, 600), 256>>>(h1, W_zx2, h2, Mrows, Hh, Hh, Hh, Hh, Hh, b_zx2, 1);

    // ytmp = exp(h2 @ W_gy^T + b)  (M=76800, N=513, K=128)
    gemm128<<<dim3(5, 600), 256>>>(h2, W_gy, ytmp, Mrows, XD, Hh, Hh, Hh, XD, b_gy, 2);

    transpose_y<<<tp_grid, tp_blk>>>(ytmp, out);
}

// round 9
// speedup vs baseline: 1.9882x; 1.0425x over previous
#include <cuda_runtime.h>
#include <cuda_bf16.h>
#include <math.h>

#define Bb 256
#define Tt 300
#define XD 513
#define ZD 16
#define Hh 128
#define G4 512          // 4*H
#define Mrows (Tt*Bb)   // 76800
#define KP 528          // padded K for the big GEMM (multiple of 16, float4-aligned)

// ---- output layout (flat concat, float32) ----
#define OFF_Y        0ull
#define OFF_ZMEAN    39398400ull
#define OFF_ZLOGVAR  40627200ull
#define OFF_ZMEANP   41856000ull
#define OFF_ZLOGVARP 43084800ull
#define OFF_ZOUT     44313600ull

// ---- scratch (device globals; zero-initialized at module load => pad cols stay 0) ----
__device__ float d_xT  [(size_t)Mrows*KP];   // (T*B, 528) padded
__device__ float d_Wp  [(size_t)G4*KP];      // (512, 528) padded W_ih
__device__ float d_bc  [G4];                 // b_ih + b_hh
__device__ float d_Gin [(size_t)Mrows*G4];   // (T,B,512)
__device__ float d_WhhT[(size_t)Hh*G4];      // (128,512) transposed W_hh
__device__ float d_hall[(size_t)Mrows*Hh];   // (T,B,128)
__device__ float d_zbuf[(size_t)Mrows*ZD];   // (T,B,16)
__device__ float d_h1  [(size_t)Mrows*Hh];
__device__ float d_h2  [(size_t)Mrows*Hh];
__device__ float d_ytmp[(size_t)Mrows*XD];   // (T,B,XD)

__device__ __forceinline__ float sigmf(float x) { return 1.0f/(1.0f + expf(-x)); }

// ============ transpose x: (B,XD,T) -> (T*B, KP) padded ============
__global__ void transpose_x(const float* __restrict__ x, float* __restrict__ xT) {
    __shared__ float tile[32][33];
    int b = blockIdx.z;
    int t0 = blockIdx.x*32, d0 = blockIdx.y*32;
    for (int i = threadIdx.y; i < 32; i += 8) {
        int d = d0 + i, t = t0 + threadIdx.x;
        if (d < XD && t < Tt) tile[i][threadIdx.x] = x[((size_t)b*XD + d)*Tt + t];
    }
    __syncthreads();
    for (int i = threadIdx.y; i < 32; i += 8) {
        int t = t0 + i, d = d0 + threadIdx.x;
        if (t < Tt && d < XD) xT[((size_t)t*Bb + b)*KP + d] = tile[threadIdx.x][i];
    }
}

// ============ prep: pad W_ih into (512,KP), combine biases ============
__global__ void prep_w(const float* __restrict__ W, const float* __restrict__ bi,
                       const float* __restrict__ bh, float* __restrict__ Wp,
                       float* __restrict__ bc) {
    int idx = blockIdx.x*256 + threadIdx.x;
    if (idx < G4*XD) {
        int n = idx / XD, k = idx % XD;
        Wp[(size_t)n*KP + k] = W[idx];
    }
    if (idx < G4) bc[idx] = bi[idx] + bh[idx];
}

// ============ transpose y: (T,B,XD) -> (B,XD,T) ============
__global__ void transpose_y(const float* __restrict__ yt, float* __restrict__ y) {
    __shared__ float tile[32][33];
    int b = blockIdx.z;
    int t0 = blockIdx.x*32, d0 = blockIdx.y*32;
    for (int i = threadIdx.y; i < 32; i += 8) {
        int t = t0 + i, d = d0 + threadIdx.x;
        if (t < Tt && d < XD) tile[i][threadIdx.x] = yt[((size_t)t*Bb + b)*XD + d];
    }
    __syncthreads();
    for (int i = threadIdx.y; i < 32; i += 8) {
        int d = d0 + i, t = t0 + threadIdx.x;
        if (d < XD && t < Tt) y[((size_t)b*XD + d)*Tt + t] = tile[threadIdx.x][i];
    }
}

// ============ transpose W_hh: (512,128) -> (128,512) ============
__global__ void transpose_whh(const float* __restrict__ W, float* __restrict__ WT) {
    int idx = blockIdx.x*256 + threadIdx.x;   // 65536 total
    int j = idx >> 7, k = idx & 127;
    WT[k*G4 + j] = W[idx];
}

// ============ 128x128-tile NT SGEMM, double-buffered ============
// C[m][n] = act(sum_k A[m][k]*Bm[n][k] + bias), A: M x lda, Bm: N x ldb (row-major).
// Requires: K % 16 == 0, M % 128 == 0, lda/ldb % 4 == 0.
// act: 0=none 1=tanh 2=exp. 256 threads, 8x8 fragments (split 4+4 for coalesced stores).
__global__ void __launch_bounds__(256, 2)
gemm128(const float* __restrict__ A, const float* __restrict__ Bm,
        float* __restrict__ C, int M, int N, int K,
        int lda, int ldb, int ldc,
        const float* __restrict__ bias, int act) {
    __shared__ float As[2][16][128];
    __shared__ float Bs[2][16][128];
    int tid = threadIdx.x;
    int m0 = blockIdx.y*128, n0 = blockIdx.x*128;
    int tm4 = (tid >> 4) * 4;       // 0..60
    int tn4 = (tid & 15) * 4;       // 0..60
    int lr = tid >> 1;              // 0..127  (each thread owns one A row + one B row per buffer)
    int lq = (tid & 1) * 2;         // 0 or 2  -> two float4 chunks per row half
    float acc[8][8] = {};
    float4 pa[2], pb[2];

    // fetch tile k0=0 into regs
    {
        int m = m0 + lr, n = n0 + lr;
        #pragma unroll
        for (int i = 0; i < 2; i++) {
            int q = lq + i;
            pa[i] = *(const float4*)(A + (size_t)m*lda + q*4);
            pb[i] = (n < N) ? *(const float4*)(Bm + (size_t)n*ldb + q*4)
                            : make_float4(0.f,0.f,0.f,0.f);
        }
    }
    int cur = 0;
    // commit buffer 0
    #pragma unroll
    for (int i = 0; i < 2; i++) {
        int q = lq + i;
        As[0][q*4+0][lr]=pa[i].x; As[0][q*4+1][lr]=pa[i].y; As[0][q*4+2][lr]=pa[i].z; As[0][q*4+3][lr]=pa[i].w;
        Bs[0][q*4+0][lr]=pb[i].x; Bs[0][q*4+1][lr]=pb[i].y; Bs[0][q*4+2][lr]=pb[i].z; Bs[0][q*4+3][lr]=pb[i].w;
    }
    __syncthreads();

    for (int k0 = 0; k0 < K; k0 += 16) {
        // prefetch next tile
        if (k0 + 16 < K) {
            int m = m0 + lr, n = n0 + lr;
            #pragma unroll
            for (int i = 0; i < 2; i++) {
                int q = lq + i;
                pa[i] = *(const float4*)(A + (size_t)m*lda + k0 + 16 + q*4);
                pb[i] = (n < N) ? *(const float4*)(Bm + (size_t)n*ldb + k0 + 16 + q*4)
                                : make_float4(0.f,0.f,0.f,0.f);
            }
        }
        // compute current buffer
        #pragma unroll
        for (int k = 0; k < 16; k++) {
            float a[8], b[8];
            *(float4*)&a[0] = *(const float4*)&As[cur][k][tm4];
            *(float4*)&a[4] = *(const float4*)&As[cur][k][tm4 + 64];
            *(float4*)&b[0] = *(const float4*)&Bs[cur][k][tn4];
            *(float4*)&b[4] = *(const float4*)&Bs[cur][k][tn4 + 64];
            #pragma unroll
            for (int i = 0; i < 8; i++)
                #pragma unroll
                for (int j = 0; j < 8; j++)
                    acc[i][j] += a[i]*b[j];
        }
        // commit prefetched tile into alternate buffer (safe: different buffer)
        if (k0 + 16 < K) {
            int nb = cur ^ 1;
            #pragma unroll
            for (int i = 0; i < 2; i++) {
                int q = lq + i;
                As[nb][q*4+0][lr]=pa[i].x; As[nb][q*4+1][lr]=pa[i].y; As[nb][q*4+2][lr]=pa[i].z; As[nb][q*4+3][lr]=pa[i].w;
                Bs[nb][q*4+0][lr]=pb[i].x; Bs[nb][q*4+1][lr]=pb[i].y; Bs[nb][q*4+2][lr]=pb[i].z; Bs[nb][q*4+3][lr]=pb[i].w;
            }
            __syncthreads();
            cur = nb;
        }
    }
    // epilogue: scalar stores, coalesced across the warp
    #pragma unroll
    for (int i = 0; i < 8; i++) {
        int m = m0 + ((i < 4) ? (tm4 + i) : (64 + tm4 + i - 4));
        float* crow = C + (size_t)m*ldc;
        #pragma unroll
        for (int j = 0; j < 8; j++) {
            int n = n0 + ((j < 4) ? (tn4 + j) : (64 + tn4 + j - 4));
            if (n >= N) continue;
            float v = acc[i][j];
            if (bias) v += bias[n];
            if (act == 1)      v = tanhf(v);
            else if (act == 2) v = expf(v);
            crow[n] = v;
        }
    }
}

// ============ LSTM over reversed time: 512 threads, 4 batch rows per CTA ============
// thread -> (col-pair cp = tid&255 : cols {2cp,2cp+1}, batch-pair bp = tid>>8 : rows {2bp,2bp+1})
// double-buffered weight smem, one sync per chunk; Gin prefetched one step ahead.
__global__ void __launch_bounds__(512, 1)
lstm_bwd(const float* __restrict__ Gin, const float* __restrict__ WhhT,
         float* __restrict__ hall) {
    __shared__ float h_s[4][Hh];
    __shared__ float c_s[4][Hh];
    __shared__ float w_s[2][16*G4];  // 2 x 32KB
    __shared__ float gate_s[4][G4];  // 8KB
    int tid = threadIdx.x;           // 512
    int b0 = blockIdx.x * 4;
    if (tid < 4*Hh) { (&h_s[0][0])[tid] = 0.0f; (&c_s[0][0])[tid] = 0.0f; }
    __syncthreads();
    int cp = tid & 255;   // col pair
    int bp = tid >> 8;    // batch pair
    // prefetch weight chunk kc=0 into registers (16x512 floats / 512 thr = 4 float4 each)
    float4 r[4];
    #pragma unroll
    for (int q = 0; q < 4; q++)
        r[q] = *(const float4*)&WhhT[(size_t)tid*4 + q*2048];
    // prefetch Gin for first step (t = Tt-1)
    float2 gp[2];
    {
        const float* gin = Gin + ((size_t)(Tt-1)*Bb + b0)*G4;
        gp[0] = *(const float2*)(gin + (2*bp  )*G4 + 2*cp);
        gp[1] = *(const float2*)(gin + (2*bp+1)*G4 + 2*cp);
    }
    int buf = 0;
    for (int t = Tt-1; t >= 0; t--) {
        float2 acc0 = gp[0];
        float2 acc1 = gp[1];
        for (int kc = 0; kc < Hh; kc += 16) {
            // commit prefetched weight chunk
            #pragma unroll
            for (int q = 0; q < 4; q++)
                *(float4*)&w_s[buf][tid*4 + q*2048] = r[q];
            __syncthreads();
            // prefetch next weight chunk (wraps to chunk 0 for next t)
            int kn = (kc + 16 < Hh) ? kc + 16 : 0;
            #pragma unroll
            for (int q = 0; q < 4; q++)
                r[q] = *(const float4*)&WhhT[(size_t)kn*G4 + tid*4 + q*2048];
            // prefetch next step's Gin during first chunk
            if (kc == 0) {
                int tn = (t > 0) ? t - 1 : 0;
                const float* gin = Gin + ((size_t)tn*Bb + b0)*G4;
                gp[0] = *(const float2*)(gin + (2*bp  )*G4 + 2*cp);
                gp[1] = *(const float2*)(gin + (2*bp+1)*G4 + 2*cp);
            }
            // compute
            const float* wb = &w_s[buf][0];
            #pragma unroll
            for (int kk = 0; kk < 16; kk++) {
                float2 w = *(const float2*)&wb[kk*G4 + 2*cp];
                float ha = h_s[2*bp  ][kc+kk];
                float hb = h_s[2*bp+1][kc+kk];
                acc0.x += w.x*ha; acc0.y += w.y*ha;
                acc1.x += w.x*hb; acc1.y += w.y*hb;
            }
            buf ^= 1;
        }
        *(float2*)&gate_s[2*bp  ][2*cp] = acc0;
        *(float2*)&gate_s[2*bp+1][2*cp] = acc1;
        __syncthreads();
        {
            int bi = tid >> 7, u = tid & 127;
            float gi = gate_s[bi][u];
            float gf = gate_s[bi][u+128];
            float gg = gate_s[bi][u+256];
            float go = gate_s[bi][u+384];
            float c = sigmf(gf)*c_s[bi][u] + sigmf(gi)*tanhf(gg);
            float h = sigmf(go)*tanhf(c);
            c_s[bi][u] = c;
            h_s[bi][u] = h;
            hall[((size_t)t*Bb + (b0+bi))*Hh + u] = h;
        }
        __syncthreads();
    }
}

// ============ inference scan (forward over t), one CTA per batch row ============
__global__ void inf_scan(const float* __restrict__ hall, const float* __restrict__ eps,
                         const float* __restrict__ Wzz, const float* __restrict__ bzz,
                         const float* __restrict__ Wim, const float* __restrict__ bim,
                         const float* __restrict__ Wil, const float* __restrict__ bil,
                         float* __restrict__ zbuf, float* __restrict__ out) {
    __shared__ float wzz_s[Hh*ZD], wim_s[ZD*Hh], wil_s[ZD*Hh];
    __shared__ float bzz_s[Hh], bim_s[ZD], bil_s[ZD];
    __shared__ float z_s[ZD], gt_s[Hh], red_s[32];
    int tid = threadIdx.x;  // 128
    int b = blockIdx.x;
    for (int i = tid; i < Hh*ZD; i += 128) { wzz_s[i] = Wzz[i]; wim_s[i] = Wim[i]; wil_s[i] = Wil[i]; }
    bzz_s[tid] = bzz[tid];
    if (tid < ZD) { bim_s[tid] = bim[tid]; bil_s[tid] = bil[tid]; z_s[tid] = 0.0f; }
    __syncthreads();
    int o = tid >> 2, p = tid & 3;
    float hcur = hall[(size_t)b*Hh + tid];   // t=0 row
    for (int t = 0; t < Tt; t++) {
        float hnext = (t+1 < Tt) ? hall[((size_t)(t+1)*Bb + b)*Hh + tid] : 0.0f;
        float a = bzz_s[tid];
        #pragma unroll
        for (int k = 0; k < ZD; k++) a += z_s[k]*wzz_s[tid*ZD + k];
        float gt = 0.5f*(tanhf(a) + hcur);
        gt_s[tid] = gt;
        __syncthreads();
        const float* wrow = (o < 16) ? (wim_s + o*Hh) : (wil_s + (o-16)*Hh);
        float s = 0.0f;
        #pragma unroll
        for (int k = 0; k < 32; k++) s += gt_s[p*32 + k]*wrow[p*32 + k];
        s += __shfl_xor_sync(0xFFFFFFFFu, s, 1);
        s += __shfl_xor_sync(0xFFFFFFFFu, s, 2);
        if (p == 0) red_s[o] = s;
        __syncthreads();
        if (tid < ZD) {
            float mean   = red_s[tid]      + bim_s[tid];
            float logvar = red_s[16 + tid] + bil_s[tid];
            size_t base = ((size_t)t*Bb + b)*ZD + tid;
            float z = mean + eps[base]*expf(0.5f*logvar);
            z_s[tid] = z;
            out[OFF_ZMEAN   + base] = mean;
            out[OFF_ZLOGVAR + base] = logvar;
            zbuf[base] = z;
            out[OFF_ZOUT + ((size_t)b*ZD + tid)*Tt + t] = z;
        }
        hcur = hnext;
        __syncthreads();
    }
}

// ============ small generation chain (16-dim MLPs), one row per thread ============
__global__ void gen_small(const float* __restrict__ zbuf,
                          const float* __restrict__ Wg1, const float* __restrict__ bg1,
                          const float* __restrict__ Wg2, const float* __restrict__ bg2,
                          const float* __restrict__ Wp1, const float* __restrict__ bp1,
                          const float* __restrict__ Wp2, const float* __restrict__ bp2,
                          const float* __restrict__ Wpm, const float* __restrict__ bpm,
                          const float* __restrict__ Wpl, const float* __restrict__ bpl,
                          float* __restrict__ out) {
    __shared__ float wg1[256], wg2[256], wp1[256], wp2[256], wpm[256], wpl[256];
    __shared__ float sb[96];
    int tid = threadIdx.x;  // 256
    wg1[tid] = Wg1[tid]; wg2[tid] = Wg2[tid]; wp1[tid] = Wp1[tid];
    wp2[tid] = Wp2[tid]; wpm[tid] = Wpm[tid]; wpl[tid] = Wpl[tid];
    if (tid < 16) {
        sb[tid]    = bg1[tid]; sb[16+tid] = bg2[tid]; sb[32+tid] = bp1[tid];
        sb[48+tid] = bp2[tid]; sb[64+tid] = bpm[tid]; sb[80+tid] = bpl[tid];
    }
    __syncthreads();
    size_t m = (size_t)blockIdx.x*256 + tid;
    float z[16], t1[16], gate[16], zp[16], zmp[16], zlv[16];
    #pragma unroll
    for (int q = 0; q < 4; q++) *(float4*)&z[q*4] = *(const float4*)(zbuf + m*16 + q*4);
    #pragma unroll
    for (int j = 0; j < 16; j++) {
        float s = sb[j];
        #pragma unroll
        for (int k = 0; k < 16; k++) s += z[k]*wg1[j*16+k];
        t1[j] = fmaxf(s, 0.0f);
    }
    #pragma unroll
    for (int j = 0; j < 16; j++) {
        float s = sb[16+j];
        #pragma unroll
        for (int k = 0; k < 16; k++) s += t1[k]*wg2[j*16+k];
        gate[j] = sigmf(s);
    }
    #pragma unroll
    for (int j = 0; j < 16; j++) {
        float s = sb[32+j];
        #pragma unroll
        for (int k = 0; k < 16; k++) s += z[k]*wp1[j*16+k];
        t1[j] = fmaxf(s, 0.0f);
    }
    #pragma unroll
    for (int j = 0; j < 16; j++) {
        float s = sb[48+j];
        #pragma unroll
        for (int k = 0; k < 16; k++) s += t1[k]*wp2[j*16+k];
        zp[j] = s;
    }
    #pragma unroll
    for (int j = 0; j < 16; j++) {
        float s = sb[64+j];
        #pragma unroll
        for (int k = 0; k < 16; k++) s += z[k]*wpm[j*16+k];
        zmp[j] = (1.0f - gate[j])*s + gate[j]*zp[j];
    }
    #pragma unroll
    for (int j = 0; j < 16; j++) t1[j] = fmaxf(zp[j], 0.0f);
    #pragma unroll
    for (int j = 0; j < 16; j++) {
        float s = sb[80+j];
        #pragma unroll
        for (int k = 0; k < 16; k++) s += t1[k]*wpl[j*16+k];
        float sp = (s > 20.0f) ? s : log1pf(expf(s));
        zlv[j] = logf(sp);
    }
    #pragma unroll
    for (int q = 0; q < 4; q++) {
        *(float4*)(out + OFF_ZMEANP   + m*16 + q*4) = *(float4*)&zmp[q*4];
        *(float4*)(out + OFF_ZLOGVARP + m*16 + q*4) = *(float4*)&zlv[q*4];
    }
}

// ============ h1 = tanh(z @ W_zx1^T + b): K=16, N=128; 4 rows per CTA ============
__global__ void h1_kernel(const float* __restrict__ zbuf, const float* __restrict__ W,
                          const float* __restrict__ bias, float* __restrict__ h1) {
    __shared__ float w_s[Hh*ZD];
    __shared__ float b_s[Hh];
    __shared__ float z_s[4][ZD];
    int tid = threadIdx.x;  // 512
    for (int i = tid; i < Hh*ZD; i += 512) w_s[i] = W[i];
    if (tid < Hh) b_s[tid] = bias[tid];
    size_t m0 = (size_t)blockIdx.x*4;
    if (tid < 64) (&z_s[0][0])[tid] = zbuf[m0*ZD + tid];
    __syncthreads();
    int r = tid >> 7, n = tid & 127;
    float a = b_s[n];
    #pragma unroll
    for (int k = 0; k < ZD; k++) a += z_s[r][k]*w_s[n*ZD + k];
    h1[(m0 + r)*Hh + n] = tanhf(a);
}

// =====================================================================
extern "C" void kernel_launch(void* const* d_in, const int* in_sizes, int n_in,
                              void* d_out, int out_size) {
    const float* x    = (const float*)d_in[0];
    const float* eps  = (const float*)d_in[1];
    const float* W_ih = (const float*)d_in[2];
    const float* W_hh = (const float*)d_in[3];
    const float* b_ih = (const float*)d_in[4];
    const float* b_hh = (const float*)d_in[5];
    const float* W_zz = (const float*)d_in[6];
    const float* b_zz = (const float*)d_in[7];
    const float* W_im = (const float*)d_in[8];
    const float* b_im = (const float*)d_in[9];
    const float* W_il = (const float*)d_in[10];
    const float* b_il = (const float*)d_in[11];
    const float* W_g1 = (const float*)d_in[12];
    const float* b_g1 = (const float*)d_in[13];
    const float* W_g2 = (const float*)d_in[14];
    const float* b_g2 = (const float*)d_in[15];
    const float* W_p1 = (const float*)d_in[16];
    const float* b_p1 = (const float*)d_in[17];
    const float* W_p2 = (const float*)d_in[18];
    const float* b_p2 = (const float*)d_in[19];
    const float* W_pm = (const float*)d_in[20];
    const float* b_pm = (const float*)d_in[21];
    const float* W_pl = (const float*)d_in[22];
    const float* b_pl = (const float*)d_in[23];
    const float* W_zx1= (const float*)d_in[24];
    const float* b_zx1= (const float*)d_in[25];
    const float* W_zx2= (const float*)d_in[26];
    const float* b_zx2= (const float*)d_in[27];
    const float* W_gy = (const float*)d_in[28];
    const float* b_gy = (const float*)d_in[29];
    float* out = (float*)d_out;

    float *xT, *Wp, *bc, *Gin, *WhhT, *hall, *zbuf, *h1, *h2, *ytmp;
    cudaGetSymbolAddress((void**)&xT,   d_xT);
    cudaGetSymbolAddress((void**)&Wp,   d_Wp);
    cudaGetSymbolAddress((void**)&bc,   d_bc);
    cudaGetSymbolAddress((void**)&Gin,  d_Gin);
    cudaGetSymbolAddress((void**)&WhhT, d_WhhT);
    cudaGetSymbolAddress((void**)&hall, d_hall);
    cudaGetSymbolAddress((void**)&zbuf, d_zbuf);
    cudaGetSymbolAddress((void**)&h1,   d_h1);
    cudaGetSymbolAddress((void**)&h2,   d_h2);
    cudaGetSymbolAddress((void**)&ytmp, d_ytmp);

    dim3 tp_grid(10, 17, Bb), tp_blk(32, 8);
    transpose_x<<<tp_grid, tp_blk>>>(x, xT);
    prep_w<<<(G4*XD + 255)/256, 256>>>(W_ih, b_ih, b_hh, Wp, bc);
    transpose_whh<<<256, 256>>>(W_hh, WhhT);

    // Gin = xT @ Wp^T + (b_ih + b_hh)   (M=76800, N=512, K=528 padded)
    gemm128<<<dim3(4, 600), 256>>>(xT, Wp, Gin, Mrows, G4, KP, KP, KP, G4, bc, 0);

    lstm_bwd<<<64, 512>>>(Gin, WhhT, hall);

    inf_scan<<<Bb, 128>>>(hall, eps, W_zz, b_zz, W_im, b_im, W_il, b_il, zbuf, out);

    gen_small<<<300, 256>>>(zbuf, W_g1, b_g1, W_g2, b_g2, W_p1, b_p1, W_p2, b_p2,
                            W_pm, b_pm, W_pl, b_pl, out);

    h1_kernel<<<Mrows/4, 512>>>(zbuf, W_zx1, b_zx1, h1);

    // h2 = tanh(h1 @ W_zx2^T + b)  (M=76800, N=128, K=128)
    gemm128<<<dim3(1, 600), 256>>>(h1, W_zx2, h2, Mrows, Hh, Hh, Hh, Hh, Hh, b_zx2, 1);

    // ytmp = exp(h2 @ W_gy^T + b)  (M=76800, N=513, K=128)
    gemm128<<<dim3(5, 600), 256>>>(h2, W_gy, ytmp, Mrows, XD, Hh, Hh, Hh, XD, b_gy, 2);

    transpose_y<<<tp_grid, tp_blk>>>(ytmp, out);
}